// round 1
// baseline (speedup 1.0000x reference)
#include <cuda_runtime.h>
#include <cstdint>

// Per-row nonlinear scan:
//   w[0] = 1; w[k] = w[k-1] + a/w[k-1] - b*x[k-1]
// rows = 32768 (l*p*m), n = 1024. One thread owns one row.
// Memory access is transposed through shared memory in 32x32 tiles so that
// global loads/stores are fully coalesced (float4), while each thread reads
// its row sequentially from smem (33-col pad -> conflict-free both phases).

#define N_COLS 1024
#define WARPS_PER_BLOCK 4
#define TILE 32

__global__ __launch_bounds__(WARPS_PER_BLOCK * 32, 1)
void DDK_77644418777662_kernel(const float* __restrict__ x,
                               const float* __restrict__ alpha,
                               const float* __restrict__ beta,
                               float* __restrict__ out,
                               int rows) {
    // one 32x33 tile per warp (disjoint regions -> __syncwarp is enough)
    __shared__ float sh[WARPS_PER_BLOCK][TILE][TILE + 1];

    const int warp = threadIdx.x >> 5;
    const int lane = threadIdx.x & 31;
    const int rowBase = (blockIdx.x * WARPS_PER_BLOCK + warp) * TILE;
    if (rowBase >= rows) return;

    const float a = __ldg(alpha);
    const float b = __ldg(beta);

    const float* xrow = x + (size_t)rowBase * N_COLS;
    float* orow       = out + (size_t)rowBase * N_COLS;

    // cooperative tile indexing: 32 lanes = 4 rows x 8 float4-chunks per pass
    const int tr_base = lane >> 3;   // 0..3  (row offset within a 4-row group)
    const int tc      = lane & 7;    // 0..7  (float4 index within row)

    float w = 1.0f;

    for (int c0 = 0; c0 < N_COLS; c0 += TILE) {
        // ---- coalesced load: 32 rows x 32 cols of input ----
        #pragma unroll
        for (int g = 0; g < TILE / 4; g++) {
            const int r = g * 4 + tr_base;
            float4 v = *(const float4*)(xrow + (size_t)r * N_COLS + c0 + tc * 4);
            sh[warp][r][tc * 4 + 0] = v.x;
            sh[warp][r][tc * 4 + 1] = v.y;
            sh[warp][r][tc * 4 + 2] = v.z;
            sh[warp][r][tc * 4 + 3] = v.w;
        }
        __syncwarp();

        // ---- sequential recurrence over this tile's 32 steps ----
        // out[k] = w (pre-update), then w <- w + a/w - b*x[k] (skip k == N-1)
        #pragma unroll
        for (int j = 0; j < TILE; j++) {
            const float xv = sh[warp][lane][j];
            sh[warp][lane][j] = w;                 // overwrite in place
            const int k = c0 + j;
            if (k < N_COLS - 1) {
                w = w + a / w - b * xv;            // IEEE div, reference order
            }
        }
        __syncwarp();

        // ---- coalesced store: 32 rows x 32 cols of output ----
        #pragma unroll
        for (int g = 0; g < TILE / 4; g++) {
            const int r = g * 4 + tr_base;
            float4 v;
            v.x = sh[warp][r][tc * 4 + 0];
            v.y = sh[warp][r][tc * 4 + 1];
            v.z = sh[warp][r][tc * 4 + 2];
            v.w = sh[warp][r][tc * 4 + 3];
            *(float4*)(orow + (size_t)r * N_COLS + c0 + tc * 4) = v;
        }
        __syncwarp();
    }
}

extern "C" void kernel_launch(void* const* d_in, const int* in_sizes, int n_in,
                              void* d_out, int out_size) {
    const float* x     = (const float*)d_in[0];
    const float* alpha = (const float*)d_in[1];
    const float* beta  = (const float*)d_in[2];
    float* out         = (float*)d_out;

    const int rows = out_size / N_COLS;                 // 32768
    const int rowsPerBlock = WARPS_PER_BLOCK * TILE;    // 128
    const int blocks = (rows + rowsPerBlock - 1) / rowsPerBlock;  // 256

    DDK_77644418777662_kernel<<<blocks, WARPS_PER_BLOCK * 32>>>(x, alpha, beta, out, rows);
}

// round 2
// speedup vs baseline: 1.4236x; 1.4236x over previous
#include <cuda_runtime.h>
#include <cstdint>

// Per-row nonlinear scan:
//   w[0] = 1; w[k] = w[k-1] + a/w[k-1] - b*x[k-1]
// rows = 32768, n = 1024. One thread per row; 32x32 smem transpose tiles for
// coalesced gmem access. Round 2: software pipeline — prefetch next tile's
// gmem data into registers during the current tile's 32-step divide chain
// (~1150 dependent cycles of shadow), hiding DRAM latency entirely.

#define N_COLS 1024
#define WARPS_PER_BLOCK 4
#define TILE 32

__global__ __launch_bounds__(WARPS_PER_BLOCK * 32)
void DDK_77644418777662_kernel(const float* __restrict__ x,
                               const float* __restrict__ alpha,
                               const float* __restrict__ beta,
                               float* __restrict__ out,
                               int rows) {
    // one 32x33 tile per warp (disjoint regions -> __syncwarp suffices)
    __shared__ float sh[WARPS_PER_BLOCK][TILE][TILE + 1];

    const int warp = threadIdx.x >> 5;
    const int lane = threadIdx.x & 31;
    const int rowBase = (blockIdx.x * WARPS_PER_BLOCK + warp) * TILE;
    if (rowBase >= rows) return;

    const float a = __ldg(alpha);
    const float b = __ldg(beta);

    const float* xrow = x + (size_t)rowBase * N_COLS;
    float* orow       = out + (size_t)rowBase * N_COLS;

    // cooperative tile indexing: 32 lanes = 4 rows x 8 float4-chunks per pass
    const int tr = lane >> 3;   // 0..3 row offset within 4-row group
    const int tc = lane & 7;    // 0..7 float4 index within row

    float4 pf[8];

    // ---- prologue: load tile 0 into registers, commit to smem ----
    #pragma unroll
    for (int g = 0; g < 8; g++)
        pf[g] = *(const float4*)(xrow + (size_t)(g * 4 + tr) * N_COLS + tc * 4);
    #pragma unroll
    for (int g = 0; g < 8; g++) {
        const int r = g * 4 + tr;
        sh[warp][r][tc * 4 + 0] = pf[g].x;
        sh[warp][r][tc * 4 + 1] = pf[g].y;
        sh[warp][r][tc * 4 + 2] = pf[g].z;
        sh[warp][r][tc * 4 + 3] = pf[g].w;
    }
    __syncwarp();

    float w = 1.0f;

    for (int c0 = 0; c0 < N_COLS; c0 += TILE) {
        const int next = c0 + TILE;

        // ---- issue next tile's loads: 8 independent LDG.128, fly during compute ----
        if (next < N_COLS) {
            #pragma unroll
            for (int g = 0; g < 8; g++)
                pf[g] = *(const float4*)(xrow + (size_t)(g * 4 + tr) * N_COLS
                                         + next + tc * 4);
        }

        // ---- 32 sequential recurrence steps (the dependent chain) ----
        // out[k] = w (pre-update), overwrite smem in place.
        // Last global step's update is computed but never stored (harmless).
        #pragma unroll
        for (int j = 0; j < TILE; j++) {
            const float xv = sh[warp][lane][j];
            sh[warp][lane][j] = w;
            w = w + a / w - b * xv;   // EXACT expression from round 1 (rel_err 0.0)
        }
        __syncwarp();

        // ---- coalesced store of this tile's outputs ----
        #pragma unroll
        for (int g = 0; g < 8; g++) {
            const int r = g * 4 + tr;
            float4 v;
            v.x = sh[warp][r][tc * 4 + 0];
            v.y = sh[warp][r][tc * 4 + 1];
            v.z = sh[warp][r][tc * 4 + 2];
            v.w = sh[warp][r][tc * 4 + 3];
            *(float4*)(orow + (size_t)r * N_COLS + c0 + tc * 4) = v;
        }
        __syncwarp();

        // ---- commit prefetched registers to smem for the next iteration ----
        if (next < N_COLS) {
            #pragma unroll
            for (int g = 0; g < 8; g++) {
                const int r = g * 4 + tr;
                sh[warp][r][tc * 4 + 0] = pf[g].x;
                sh[warp][r][tc * 4 + 1] = pf[g].y;
                sh[warp][r][tc * 4 + 2] = pf[g].z;
                sh[warp][r][tc * 4 + 3] = pf[g].w;
            }
            __syncwarp();
        }
    }
}

extern "C" void kernel_launch(void* const* d_in, const int* in_sizes, int n_in,
                              void* d_out, int out_size) {
    const float* x     = (const float*)d_in[0];
    const float* alpha = (const float*)d_in[1];
    const float* beta  = (const float*)d_in[2];
    float* out         = (float*)d_out;

    const int rows = out_size / N_COLS;                 // 32768
    const int rowsPerBlock = WARPS_PER_BLOCK * TILE;    // 128
    const int blocks = (rows + rowsPerBlock - 1) / rowsPerBlock;  // 256

    DDK_77644418777662_kernel<<<blocks, WARPS_PER_BLOCK * 32>>>(x, alpha, beta, out, rows);
}